// round 4
// baseline (speedup 1.0000x reference)
#include <cuda_runtime.h>
#include <math.h>
#include <stdint.h>

#define W_IMG 2000
#define H_IMG 1500
#define HW_IMG (W_IMG * H_IMG)
#define NUM_VV 10
#define EPSF 1e-6f

// ---------------- global accumulators (zero at load; fin_k re-zeros) --------
__device__ double g_sim;
__device__ double g_norm;
__device__ double g_normz;
__device__ unsigned long long g_count;

// ---------------- bilinear 3-channel sample (plain loads, R1 style) ---------
__device__ __forceinline__ void sample3(const float* __restrict__ im, float u, float v,
                                        float& c0, float& c1, float& c2) {
    float x = u * (float)(W_IMG - 1);
    float y = v * (float)(H_IMG - 1);
    float xf = floorf(x), yf = floorf(y);
    int x0 = (int)xf, y0 = (int)yf;
    int x1 = min(x0 + 1, W_IMG - 1);
    int y1 = min(y0 + 1, H_IMG - 1);
    float wx = x - xf, wy = y - yf;
    float w00 = (1.0f - wx) * (1.0f - wy);
    float w10 = wx * (1.0f - wy);
    float w01 = (1.0f - wx) * wy;
    float w11 = wx * wy;
    int i00 = y0 * W_IMG + x0;
    int i01 = y0 * W_IMG + x1;
    int i10 = y1 * W_IMG + x0;
    int i11 = y1 * W_IMG + x1;
    c0 = im[i00] * w00 + im[i01] * w10 + im[i10] * w01 + im[i11] * w11;
    const float* im1 = im + HW_IMG;
    c1 = im1[i00] * w00 + im1[i01] * w10 + im1[i10] * w01 + im1[i11] * w11;
    const float* im2 = im + 2 * HW_IMG;
    c2 = im2[i00] * w00 + im2[i01] * w10 + im2[i10] * w01 + im2[i11] * w11;
}

__device__ __forceinline__ float clamp_uv(float q) {
    return fminf(fmaxf(q, 0.0f), 0.999999f);
}

// ---------------- main per-edge kernel: one block per edge -------------------
__global__ __launch_bounds__(128) void edge_k(const float* __restrict__ ep,
                                              const float* __restrict__ K1,
                                              const float* __restrict__ K2,
                                              const float* __restrict__ E1,
                                              const float* __restrict__ E2,
                                              const float* __restrict__ rgb1,
                                              const float* __restrict__ rgb2,
                                              int N) {
    __shared__ float sT[12];

    int e = blockIdx.x;
    if (e >= N) return;

    // thread 0 builds T = K2h @ E2 @ inv(E1) into shared
    if (threadIdx.x == 0) {
        float a[4][8];
        for (int i = 0; i < 4; i++)
            for (int j = 0; j < 4; j++) {
                a[i][j] = E1[i * 4 + j];
                a[i][4 + j] = (i == j) ? 1.0f : 0.0f;
            }
        for (int c = 0; c < 4; c++) {
            int piv = c;
            float best = fabsf(a[c][c]);
            for (int r = c + 1; r < 4; r++) {
                float v = fabsf(a[r][c]);
                if (v > best) { best = v; piv = r; }
            }
            if (piv != c)
                for (int j = 0; j < 8; j++) {
                    float t = a[c][j]; a[c][j] = a[piv][j]; a[piv][j] = t;
                }
            float inv_d = 1.0f / a[c][c];
            for (int j = 0; j < 8; j++) a[c][j] *= inv_d;
            for (int r = 0; r < 4; r++) {
                if (r == c) continue;
                float f = a[r][c];
                for (int j = 0; j < 8; j++) a[r][j] -= f * a[c][j];
            }
        }
        // M = E2 @ inv(E1)
        float Mm[4][4];
        for (int i = 0; i < 4; i++)
            for (int j = 0; j < 4; j++) {
                float s = 0.0f;
                for (int k = 0; k < 4; k++) s += E2[i * 4 + k] * a[k][4 + j];
                Mm[i][j] = s;
            }
        for (int i = 0; i < 3; i++)
            for (int j = 0; j < 4; j++) {
                float s = 0.0f;
                for (int k = 0; k < 3; k++) s += K2[i * 3 + k] * Mm[k][j];
                sT[i * 4 + j] = s;
            }
    }

    const float* p = ep + (size_t)e * 12;
    float p0x = p[0],  p0y = p[1],  p0z = p[2];
    float p1x = p[3],  p1y = p[4],  p1z = p[5];
    float p2x = p[6],  p2y = p[7],  p2z = p[8];
    float p3x = p[9],  p3y = p[10], p3z = p[11];

    float cdx = p1x - p0x, cdy = p1y - p0y, cdz = p1z - p0z;
    float ndx = p3x - p1x, ndy = p3y - p1y, ndz = p3z - p1z;

    // cur_len = norm(cd + EPS) with numpy rounding order (no FMA fusion)
    float ax = cdx + EPSF, ay = cdy + EPSF, az = cdz + EPSF;
    float sq = __fadd_rn(__fadd_rn(__fmul_rn(ax, ax), __fmul_rn(ay, ay)),
                         __fmul_rn(az, az));
    float cur_len = sqrtf(sq);
    float inv_len = 1.0f / cur_len;
    float dx = cdx * inv_len, dy_ = cdy * inv_len, dz = cdz * inv_len;

    // cur_normal = normalize(cross(cur_dir, next_dir)), flip if z>0
    float cnx = dy_ * ndz - dz * ndy;
    float cny = dz * ndx - dx * ndz;
    float cnz = dx * ndy - dy_ * ndx;
    {
        float nn = sqrtf(cnx * cnx + cny * cny + cnz * cnz) + EPSF;
        cnx /= nn; cny /= nn; cnz /= nn;
    }
    if (cnz > 0.0f) { cnx = -cnx; cny = -cny; cnz = -cnz; }

    // cur_up = normalize(cross(cur_normal, cur_dir))
    float cux = cny * dz - cnz * dy_;
    float cuy = cnz * dx - cnx * dz;
    float cuz = cnx * dy_ - cny * dx;
    {
        float nn = sqrtf(cux * cux + cuy * cuy + cuz * cuz) + EPSF;
        cux /= nn; cuy /= nn; cuz /= nn;
    }

    // num_h = clip(floor(cur_len / 0.05), 2, 1000)  (f64 divide matches numpy //)
    int num_h = (int)floor((double)cur_len / 0.05);
    num_h = max(2, min(1000, num_h));

    if (threadIdx.x == 0) {
        float pdx = p0x - p2x, pdy = p0y - p2y, pdz = p0z - p2z;
        float pnx = pdy * dz - pdz * dy_;
        float pny = pdz * dx - pdx * dz;
        float pnz = pdx * dy_ - pdy * dx;
        float nn = sqrtf(pnx * pnx + pny * pny + pnz * pnz) + EPSF;
        float nl = 1.0f - (cnx * pnx + cny * pny + cnz * pnz) / nn;

        float onx = p0y * p1z - p0z * p1y;
        float ony = p0z * p1x - p0x * p1z;
        float onz = p0x * p1y - p0y * p1x;
        float on = sqrtf(onx * onx + ony * ony + onz * onz) + EPSF;
        float snp = fminf(fabsf((cux * onx + cuy * ony + cuz * onz) / on), 0.5f);
        float nz = 1.0f - snp / 0.5f;

        atomicAdd(&g_norm, (double)nl);
        atomicAdd(&g_normz, (double)nz);
        atomicAdd(&g_count, (unsigned long long)num_h);
    }

    __syncthreads();  // sT ready

    // load K1 and T into registers
    float k00 = K1[0], k01 = K1[1], k02 = K1[2];
    float k10 = K1[3], k11 = K1[4], k12 = K1[5];
    float k20 = K1[6], k21 = K1[7], k22 = K1[8];
    float t00 = sT[0],  t01 = sT[1],  t02 = sT[2],  t03 = sT[3];
    float t10 = sT[4],  t11 = sT[5],  t12 = sT[6],  t13 = sT[7];
    float t20 = sT[8],  t21 = sT[9],  t22 = sT[10], t23 = sT[11];

    float step = cur_len / (float)(num_h - 1);
    int total = num_h * NUM_VV;
    float lsim = 0.0f;

    // px-fastest mapping: i = dv * num_h + px  -> adjacent lanes walk along
    // the edge (~2.5-5 px apart in the image, same rows) for sector sharing.
    uint32_t Mg = (uint32_t)((0x100000000ULL + (uint64_t)num_h - 1) / (uint64_t)num_h);

    for (int i = threadIdx.x; i < total; i += 128) {
        int dv = (int)__umulhi((uint32_t)i, Mg);  // i / num_h
        int px = i - dv * num_h;                  // i % num_h (fast index)
        float cx = (float)px * step;
        float cy = (float)dv * (0.5f / 9.0f);

        float ptx = dx * cx + cux * cy + p0x;
        float pty = dy_ * cx + cuy * cy + p0y;
        float ptz = dz * cx + cuz * cy + p0z;

        // projection 1: uv1 = K1 * pt
        float z1 = k20 * ptx + k21 * pty + k22 * ptz;
        float rz1 = __fdividef(1.0f, z1);
        float u1 = clamp_uv((k00 * ptx + k01 * pty + k02 * ptz) * rz1);
        float v1 = clamp_uv((k10 * ptx + k11 * pty + k12 * ptz) * rz1);
        float s1a, s1b, s1c;
        sample3(rgb1, u1, v1, s1a, s1b, s1c);

        // projection 2: uv2 = T * [pt, 1]
        float z2 = t20 * ptx + t21 * pty + t22 * ptz + t23;
        float rz2 = __fdividef(1.0f, z2);
        float u2 = clamp_uv((t00 * ptx + t01 * pty + t02 * ptz + t03) * rz2);
        float v2 = clamp_uv((t10 * ptx + t11 * pty + t12 * ptz + t13) * rz2);
        float s2a, s2b, s2c;
        sample3(rgb2, u2, v2, s2a, s2b, s2c);

        float d0 = s1a - s2a, d1 = s1b - s2b, d2 = s1c - s2c;
        lsim += d0 * d0 + d1 * d1 + d2 * d2;
    }

    // block reduction (convert to double at reduce)
    double dsim = (double)lsim;
    for (int o = 16; o > 0; o >>= 1)
        dsim += __shfl_down_sync(0xffffffffu, dsim, o);
    __shared__ double ssum[4];
    int lane = threadIdx.x & 31;
    int w = threadIdx.x >> 5;
    if (lane == 0) ssum[w] = dsim;
    __syncthreads();
    if (threadIdx.x == 0) {
        double t = ssum[0] + ssum[1] + ssum[2] + ssum[3];
        atomicAdd(&g_sim, t);
    }
}

// ---------------- finalize: write out, then reset accumulators ---------------
__global__ void fin_k(float* __restrict__ out, int N) {
    if (threadIdx.x != 0 || blockIdx.x != 0) return;
    double cnt = (double)g_count * (double)NUM_VV * 3.0;
    out[0] = (float)(g_sim / cnt);
    out[1] = (float)(g_norm / (double)N * 0.5);
    out[2] = (float)(g_normz / (double)N);
    // reset for the next invocation (globals start zeroed at module load)
    g_sim = 0.0; g_norm = 0.0; g_normz = 0.0; g_count = 0ull;
}

// ---------------- launch -------------------------------------------------------
extern "C" void kernel_launch(void* const* d_in, const int* in_sizes, int n_in,
                              void* d_out, int out_size) {
    const float* ep   = (const float*)d_in[0];
    const float* K1   = (const float*)d_in[1];
    const float* K2   = (const float*)d_in[2];
    const float* E1   = (const float*)d_in[3];
    const float* E2   = (const float*)d_in[4];
    const float* rgb1 = (const float*)d_in[5];
    const float* rgb2 = (const float*)d_in[6];
    float* out = (float*)d_out;

    int N = in_sizes[0] / 12;

    edge_k<<<N, 128>>>(ep, K1, K2, E1, E2, rgb1, rgb2, N);
    fin_k<<<1, 1>>>(out, N);
}

// round 6
// speedup vs baseline: 1.3206x; 1.3206x over previous
#include <cuda_runtime.h>
#include <math.h>

#define W_IMG 2000
#define H_IMG 1500
#define HW_IMG (W_IMG * H_IMG)
#define NUM_VV 10
#define EPSF 1e-6f

// ---------------- global accumulators / derived transform -------------------
__device__ double g_sim;
__device__ double g_norm;
__device__ double g_normz;
__device__ unsigned long long g_count;
__device__ float g_T[12]; // rows 0..2 of T = K2h @ E2 @ inv(E1) (4 cols each)

// ---------------- setup: invert E1, build T, zero accumulators --------------
__global__ void setup_k(const float* __restrict__ K2,
                        const float* __restrict__ E1,
                        const float* __restrict__ E2) {
    if (threadIdx.x != 0 || blockIdx.x != 0) return;
    g_sim = 0.0; g_norm = 0.0; g_normz = 0.0; g_count = 0ull;

    // Gauss-Jordan inverse of 4x4 E1 with partial pivoting
    float a[4][8];
    for (int i = 0; i < 4; i++) {
        for (int j = 0; j < 4; j++) {
            a[i][j] = E1[i * 4 + j];
            a[i][4 + j] = (i == j) ? 1.0f : 0.0f;
        }
    }
    for (int c = 0; c < 4; c++) {
        int piv = c;
        float best = fabsf(a[c][c]);
        for (int r = c + 1; r < 4; r++) {
            float v = fabsf(a[r][c]);
            if (v > best) { best = v; piv = r; }
        }
        if (piv != c) {
            for (int j = 0; j < 8; j++) {
                float t = a[c][j]; a[c][j] = a[piv][j]; a[piv][j] = t;
            }
        }
        float inv_d = 1.0f / a[c][c];
        for (int j = 0; j < 8; j++) a[c][j] *= inv_d;
        for (int r = 0; r < 4; r++) {
            if (r == c) continue;
            float f = a[r][c];
            for (int j = 0; j < 8; j++) a[r][j] -= f * a[c][j];
        }
    }
    float inv1[4][4];
    for (int i = 0; i < 4; i++)
        for (int j = 0; j < 4; j++)
            inv1[i][j] = a[i][4 + j];

    // M = E2 @ inv1
    float M[4][4];
    for (int i = 0; i < 4; i++)
        for (int j = 0; j < 4; j++) {
            float s = 0.0f;
            for (int k = 0; k < 4; k++) s += E2[i * 4 + k] * inv1[k][j];
            M[i][j] = s;
        }
    // T rows 0..2 = K2 (3x3) @ M[0..2][:]
    for (int i = 0; i < 3; i++)
        for (int j = 0; j < 4; j++) {
            float s = 0.0f;
            for (int k = 0; k < 3; k++) s += K2[i * 3 + k] * M[k][j];
            g_T[i * 4 + j] = s;
        }
}

// ---------------- bilinear 3-channel sample (plain loads) --------------------
__device__ __forceinline__ void sample3(const float* __restrict__ im, float u, float v,
                                        float& c0, float& c1, float& c2) {
    float x = u * (float)(W_IMG - 1);
    float y = v * (float)(H_IMG - 1);
    float xf = floorf(x), yf = floorf(y);
    int x0 = (int)xf, y0 = (int)yf;
    int x1 = min(x0 + 1, W_IMG - 1);
    int y1 = min(y0 + 1, H_IMG - 1);
    float wx = x - xf, wy = y - yf;
    float w00 = (1.0f - wx) * (1.0f - wy);
    float w10 = wx * (1.0f - wy);
    float w01 = (1.0f - wx) * wy;
    float w11 = wx * wy;
    int i00 = y0 * W_IMG + x0;
    int i01 = y0 * W_IMG + x1;
    int i10 = y1 * W_IMG + x0;
    int i11 = y1 * W_IMG + x1;
    c0 = im[i00] * w00 + im[i01] * w10 + im[i10] * w01 + im[i11] * w11;
    const float* im1 = im + HW_IMG;
    c1 = im1[i00] * w00 + im1[i01] * w10 + im1[i10] * w01 + im1[i11] * w11;
    const float* im2 = im + 2 * HW_IMG;
    c2 = im2[i00] * w00 + im2[i01] * w10 + im2[i10] * w01 + im2[i11] * w11;
}

__device__ __forceinline__ float clamp_uv(float q) {
    return fminf(fmaxf(q, 0.0f), 0.999999f);
}

// ---------------- main per-edge kernel (R1 structure, occ-boosted) ----------
__global__ __launch_bounds__(128, 10) void edge_k(const float* __restrict__ ep,
                                                  const float* __restrict__ K1,
                                                  const float* __restrict__ rgb1,
                                                  const float* __restrict__ rgb2,
                                                  int N) {
    int e = blockIdx.x;
    if (e >= N) return;
    const float* p = ep + (size_t)e * 12;
    float p0x = p[0],  p0y = p[1],  p0z = p[2];
    float p1x = p[3],  p1y = p[4],  p1z = p[5];
    float p2x = p[6],  p2y = p[7],  p2z = p[8];
    float p3x = p[9],  p3y = p[10], p3z = p[11];

    float cdx = p1x - p0x, cdy = p1y - p0y, cdz = p1z - p0z;
    float ndx = p3x - p1x, ndy = p3y - p1y, ndz = p3z - p1z;

    // cur_len = norm(cd + EPS) with numpy rounding order (no FMA fusion)
    float ax = cdx + EPSF, ay = cdy + EPSF, az = cdz + EPSF;
    float sq = __fadd_rn(__fadd_rn(__fmul_rn(ax, ax), __fmul_rn(ay, ay)),
                         __fmul_rn(az, az));
    float cur_len = sqrtf(sq);
    float inv_len = 1.0f / cur_len;
    float dx = cdx * inv_len, dy_ = cdy * inv_len, dz = cdz * inv_len;

    // cur_normal = normalize(cross(cur_dir, next_dir)), flip if z>0
    float cnx = dy_ * ndz - dz * ndy;
    float cny = dz * ndx - dx * ndz;
    float cnz = dx * ndy - dy_ * ndx;
    {
        float nn = sqrtf(cnx * cnx + cny * cny + cnz * cnz) + EPSF;
        cnx /= nn; cny /= nn; cnz /= nn;
    }
    if (cnz > 0.0f) { cnx = -cnx; cny = -cny; cnz = -cnz; }

    // cur_up = normalize(cross(cur_normal, cur_dir))
    float cux = cny * dz - cnz * dy_;
    float cuy = cnz * dx - cnx * dz;
    float cuz = cnx * dy_ - cny * dx;
    {
        float nn = sqrtf(cux * cux + cuy * cuy + cuz * cuz) + EPSF;
        cux /= nn; cuy /= nn; cuz /= nn;
    }

    // num_h = clip(floor(cur_len / 0.05), 2, 1000) (f64 divide matches numpy //)
    int num_h = (int)floor((double)cur_len / 0.05);
    num_h = max(2, min(1000, num_h));

    if (threadIdx.x == 0) {
        float pdx = p0x - p2x, pdy = p0y - p2y, pdz = p0z - p2z;
        float pnx = pdy * dz - pdz * dy_;
        float pny = pdz * dx - pdx * dz;
        float pnz = pdx * dy_ - pdy * dx;
        float nn = sqrtf(pnx * pnx + pny * pny + pnz * pnz) + EPSF;
        float nl = 1.0f - (cnx * pnx + cny * pny + cnz * pnz) / nn;

        float onx = p0y * p1z - p0z * p1y;
        float ony = p0z * p1x - p0x * p1z;
        float onz = p0x * p1y - p0y * p1x;
        float on = sqrtf(onx * onx + ony * ony + onz * onz) + EPSF;
        float snp = fminf(fabsf((cux * onx + cuy * ony + cuz * onz) / on), 0.5f);
        float nz = 1.0f - snp / 0.5f;

        atomicAdd(&g_norm, (double)nl);
        atomicAdd(&g_normz, (double)nz);
        atomicAdd(&g_count, (unsigned long long)num_h);
    }

    // load K1 and T into registers
    float k00 = K1[0], k01 = K1[1], k02 = K1[2];
    float k10 = K1[3], k11 = K1[4], k12 = K1[5];
    float k20 = K1[6], k21 = K1[7], k22 = K1[8];
    float t00 = g_T[0],  t01 = g_T[1],  t02 = g_T[2],  t03 = g_T[3];
    float t10 = g_T[4],  t11 = g_T[5],  t12 = g_T[6],  t13 = g_T[7];
    float t20 = g_T[8],  t21 = g_T[9],  t22 = g_T[10], t23 = g_T[11];

    float step = cur_len / (float)(num_h - 1);
    int total = num_h * NUM_VV;
    float lsim = 0.0f;

    for (int i = threadIdx.x; i < total; i += 128) {
        int px = i / NUM_VV;           // compile-time magic multiply
        int dv = i - px * NUM_VV;
        float cx = (float)px * step;
        float cy = (float)dv * (0.5f / 9.0f);

        float ptx = dx * cx + cux * cy + p0x;
        float pty = dy_ * cx + cuy * cy + p0y;
        float ptz = dz * cx + cuz * cy + p0z;

        // projection 1: uv1 = K1 * pt
        float z1 = k20 * ptx + k21 * pty + k22 * ptz;
        float rz1 = __fdividef(1.0f, z1);
        float u1 = clamp_uv((k00 * ptx + k01 * pty + k02 * ptz) * rz1);
        float v1 = clamp_uv((k10 * ptx + k11 * pty + k12 * ptz) * rz1);
        float s1a, s1b, s1c;
        sample3(rgb1, u1, v1, s1a, s1b, s1c);

        // projection 2: uv2 = T * [pt, 1]
        float z2 = t20 * ptx + t21 * pty + t22 * ptz + t23;
        float rz2 = __fdividef(1.0f, z2);
        float u2 = clamp_uv((t00 * ptx + t01 * pty + t02 * ptz + t03) * rz2);
        float v2 = clamp_uv((t10 * ptx + t11 * pty + t12 * ptz + t13) * rz2);
        float s2a, s2b, s2c;
        sample3(rgb2, u2, v2, s2a, s2b, s2c);

        float d0 = s1a - s2a, d1 = s1b - s2b, d2 = s1c - s2c;
        lsim += d0 * d0 + d1 * d1 + d2 * d2;
    }

    // block reduction (convert to double at reduce)
    double dsim = (double)lsim;
    for (int o = 16; o > 0; o >>= 1)
        dsim += __shfl_down_sync(0xffffffffu, dsim, o);
    __shared__ double ssum[4];
    int lane = threadIdx.x & 31;
    int w = threadIdx.x >> 5;
    if (lane == 0) ssum[w] = dsim;
    __syncthreads();
    if (threadIdx.x == 0) {
        double t = ssum[0] + ssum[1] + ssum[2] + ssum[3];
        atomicAdd(&g_sim, t);
    }
}

// ---------------- finalize ----------------------------------------------------
__global__ void fin_k(float* __restrict__ out, int N) {
    if (threadIdx.x != 0 || blockIdx.x != 0) return;
    double cnt = (double)g_count * (double)NUM_VV * 3.0;
    out[0] = (float)(g_sim / cnt);
    out[1] = (float)(g_norm / (double)N * 0.5);
    out[2] = (float)(g_normz / (double)N);
}

// ---------------- launch -------------------------------------------------------
extern "C" void kernel_launch(void* const* d_in, const int* in_sizes, int n_in,
                              void* d_out, int out_size) {
    const float* ep   = (const float*)d_in[0];
    const float* K1   = (const float*)d_in[1];
    const float* K2   = (const float*)d_in[2];
    const float* E1   = (const float*)d_in[3];
    const float* E2   = (const float*)d_in[4];
    const float* rgb1 = (const float*)d_in[5];
    const float* rgb2 = (const float*)d_in[6];
    float* out = (float*)d_out;

    int N = in_sizes[0] / 12;

    setup_k<<<1, 1>>>(K2, E1, E2);
    edge_k<<<N, 128>>>(ep, K1, rgb1, rgb2, N);
    fin_k<<<1, 1>>>(out, N);
}

// round 8
// speedup vs baseline: 2.1283x; 1.6115x over previous
#include <cuda_runtime.h>
#include <cuda_fp16.h>
#include <math.h>

#define W_IMG 2000
#define H_IMG 1500
#define HW_IMG (W_IMG * H_IMG)
#define NUM_VV 10
#define EPSF 1e-6f

// ---------------- global accumulators (zero at load; last block re-zeros) ---
__device__ double g_sim;
__device__ double g_norm;
__device__ double g_normz;
__device__ unsigned long long g_count;
__device__ unsigned int g_done;

// ---------------- repacked images: interleaved half4 (r,g | b,0) ------------
__device__ uint2 g_i1[HW_IMG];
__device__ uint2 g_i2[HW_IMG];

// ---------------- repack kernel ----------------------------------------------
__global__ void repack_k(const float* __restrict__ rgb1,
                         const float* __restrict__ rgb2) {
    int idx = blockIdx.x * blockDim.x + threadIdx.x;
    int stride = gridDim.x * blockDim.x;
    for (int i = idx; i < HW_IMG; i += stride) {
        float r1 = rgb1[i], gg1 = rgb1[HW_IMG + i], b1 = rgb1[2 * HW_IMG + i];
        uint2 v1;
        __half2 rg1 = __floats2half2_rn(r1, gg1);
        __half2 bz1 = __floats2half2_rn(b1, 0.0f);
        v1.x = *(unsigned int*)&rg1;
        v1.y = *(unsigned int*)&bz1;
        g_i1[i] = v1;

        float r2 = rgb2[i], gg2 = rgb2[HW_IMG + i], b2 = rgb2[2 * HW_IMG + i];
        uint2 v2;
        __half2 rg2 = __floats2half2_rn(r2, gg2);
        __half2 bz2 = __floats2half2_rn(b2, 0.0f);
        v2.x = *(unsigned int*)&rg2;
        v2.y = *(unsigned int*)&bz2;
        g_i2[i] = v2;
    }
}

// ---------------- bilinear 3-channel sample from half4 ----------------------
__device__ __forceinline__ void sample3h(const uint2* __restrict__ img, float u, float v,
                                         float& c0, float& c1, float& c2) {
    float x = u * (float)(W_IMG - 1);
    float y = v * (float)(H_IMG - 1);
    float xf = floorf(x), yf = floorf(y);
    int x0 = (int)xf, y0 = (int)yf;
    int x1 = min(x0 + 1, W_IMG - 1);
    int y1 = min(y0 + 1, H_IMG - 1);
    float wx = x - xf, wy = y - yf;
    float w00 = (1.0f - wx) * (1.0f - wy);
    float w10 = wx * (1.0f - wy);
    float w01 = (1.0f - wx) * wy;
    float w11 = wx * wy;
    int i00 = y0 * W_IMG + x0;
    int i01 = y0 * W_IMG + x1;
    int i10 = y1 * W_IMG + x0;
    int i11 = y1 * W_IMG + x1;
    uint2 q00 = img[i00], q01 = img[i01], q10 = img[i10], q11 = img[i11];
    float2 rg00 = __half22float2(*(__half2*)&q00.x);
    float2 rg01 = __half22float2(*(__half2*)&q01.x);
    float2 rg10 = __half22float2(*(__half2*)&q10.x);
    float2 rg11 = __half22float2(*(__half2*)&q11.x);
    float b00 = __low2float(*(__half2*)&q00.y);
    float b01 = __low2float(*(__half2*)&q01.y);
    float b10 = __low2float(*(__half2*)&q10.y);
    float b11 = __low2float(*(__half2*)&q11.y);
    c0 = rg00.x * w00 + rg01.x * w10 + rg10.x * w01 + rg11.x * w11;
    c1 = rg00.y * w00 + rg01.y * w10 + rg10.y * w01 + rg11.y * w11;
    c2 = b00 * w00 + b01 * w10 + b10 * w01 + b11 * w11;
}

__device__ __forceinline__ float clamp_uv(float q) {
    return fminf(fmaxf(q, 0.0f), 0.999999f);
}

// ---------------- register-only general 4x4 inverse (adjugate) --------------
__device__ __forceinline__ void inv4(const float m[16], float inv[16]) {
    inv[0] = m[5]*m[10]*m[15] - m[5]*m[11]*m[14] - m[9]*m[6]*m[15] + m[9]*m[7]*m[14] + m[13]*m[6]*m[11] - m[13]*m[7]*m[10];
    inv[4] = -m[4]*m[10]*m[15] + m[4]*m[11]*m[14] + m[8]*m[6]*m[15] - m[8]*m[7]*m[14] - m[12]*m[6]*m[11] + m[12]*m[7]*m[10];
    inv[8] = m[4]*m[9]*m[15] - m[4]*m[11]*m[13] - m[8]*m[5]*m[15] + m[8]*m[7]*m[13] + m[12]*m[5]*m[11] - m[12]*m[7]*m[9];
    inv[12] = -m[4]*m[9]*m[14] + m[4]*m[10]*m[13] + m[8]*m[5]*m[14] - m[8]*m[6]*m[13] - m[12]*m[5]*m[10] + m[12]*m[6]*m[9];
    inv[1] = -m[1]*m[10]*m[15] + m[1]*m[11]*m[14] + m[9]*m[2]*m[15] - m[9]*m[3]*m[14] - m[13]*m[2]*m[11] + m[13]*m[3]*m[10];
    inv[5] = m[0]*m[10]*m[15] - m[0]*m[11]*m[14] - m[8]*m[2]*m[15] + m[8]*m[3]*m[14] + m[12]*m[2]*m[11] - m[12]*m[3]*m[10];
    inv[9] = -m[0]*m[9]*m[15] + m[0]*m[11]*m[13] + m[8]*m[1]*m[15] - m[8]*m[3]*m[13] - m[12]*m[1]*m[11] + m[12]*m[3]*m[9];
    inv[13] = m[0]*m[9]*m[14] - m[0]*m[10]*m[13] - m[8]*m[1]*m[14] + m[8]*m[2]*m[13] + m[12]*m[1]*m[10] - m[12]*m[2]*m[9];
    inv[2] = m[1]*m[6]*m[15] - m[1]*m[7]*m[14] - m[5]*m[2]*m[15] + m[5]*m[3]*m[14] + m[13]*m[2]*m[7] - m[13]*m[3]*m[6];
    inv[6] = -m[0]*m[6]*m[15] + m[0]*m[7]*m[14] + m[4]*m[2]*m[15] - m[4]*m[3]*m[14] - m[12]*m[2]*m[7] + m[12]*m[3]*m[6];
    inv[10] = m[0]*m[5]*m[15] - m[0]*m[7]*m[13] - m[4]*m[1]*m[15] + m[4]*m[3]*m[13] + m[12]*m[1]*m[7] - m[12]*m[3]*m[5];
    inv[14] = -m[0]*m[5]*m[14] + m[0]*m[6]*m[13] + m[4]*m[1]*m[14] - m[4]*m[2]*m[13] - m[12]*m[1]*m[6] + m[12]*m[2]*m[5];
    inv[3] = -m[1]*m[6]*m[11] + m[1]*m[7]*m[10] + m[5]*m[2]*m[11] - m[5]*m[3]*m[10] - m[9]*m[2]*m[7] + m[9]*m[3]*m[6];
    inv[7] = m[0]*m[6]*m[11] - m[0]*m[7]*m[10] - m[4]*m[2]*m[11] + m[4]*m[3]*m[10] + m[8]*m[2]*m[7] - m[8]*m[3]*m[6];
    inv[11] = -m[0]*m[5]*m[11] + m[0]*m[7]*m[9] + m[4]*m[1]*m[11] - m[4]*m[3]*m[9] - m[8]*m[1]*m[7] + m[8]*m[3]*m[5];
    inv[15] = m[0]*m[5]*m[10] - m[0]*m[6]*m[9] - m[4]*m[1]*m[10] + m[4]*m[2]*m[9] + m[8]*m[1]*m[6] - m[8]*m[2]*m[5];
    float det = m[0]*inv[0] + m[1]*inv[4] + m[2]*inv[8] + m[3]*inv[12];
    float rd = 1.0f / det;
    #pragma unroll
    for (int i = 0; i < 16; i++) inv[i] *= rd;
}

// ---------------- main per-edge kernel (R1 inner loop, half4 gathers) -------
__global__ __launch_bounds__(128) void edge_k(const float* __restrict__ ep,
                                              const float* __restrict__ K1,
                                              const float* __restrict__ K2,
                                              const float* __restrict__ E1,
                                              const float* __restrict__ E2,
                                              float* __restrict__ out,
                                              int N) {
    int e = blockIdx.x;
    if (e >= N) return;

    // --- per-thread T = K2h @ E2 @ inv(E1), register-only -------------------
    float m[16], iv[16];
    #pragma unroll
    for (int i = 0; i < 16; i++) m[i] = E1[i];
    inv4(m, iv);
    float Mm[12];
    #pragma unroll
    for (int i = 0; i < 3; i++)
        #pragma unroll
        for (int j = 0; j < 4; j++) {
            float s = 0.0f;
            #pragma unroll
            for (int k = 0; k < 4; k++) s += E2[i * 4 + k] * iv[k * 4 + j];
            Mm[i * 4 + j] = s;
        }
    float T[12];
    #pragma unroll
    for (int i = 0; i < 3; i++)
        #pragma unroll
        for (int j = 0; j < 4; j++) {
            float s = 0.0f;
            #pragma unroll
            for (int k = 0; k < 3; k++) s += K2[i * 3 + k] * Mm[k * 4 + j];
            T[i * 4 + j] = s;
        }

    const float* p = ep + (size_t)e * 12;
    float p0x = p[0],  p0y = p[1],  p0z = p[2];
    float p1x = p[3],  p1y = p[4],  p1z = p[5];
    float p2x = p[6],  p2y = p[7],  p2z = p[8];
    float p3x = p[9],  p3y = p[10], p3z = p[11];

    float cdx = p1x - p0x, cdy = p1y - p0y, cdz = p1z - p0z;
    float ndx = p3x - p1x, ndy = p3y - p1y, ndz = p3z - p1z;

    float ax = cdx + EPSF, ay = cdy + EPSF, az = cdz + EPSF;
    float cur_len = sqrtf(ax * ax + ay * ay + az * az);
    float inv_len = 1.0f / cur_len;
    float dx = cdx * inv_len, dy_ = cdy * inv_len, dz = cdz * inv_len;

    float cnx = dy_ * ndz - dz * ndy;
    float cny = dz * ndx - dx * ndz;
    float cnz = dx * ndy - dy_ * ndx;
    {
        float nn = sqrtf(cnx * cnx + cny * cny + cnz * cnz) + EPSF;
        cnx /= nn; cny /= nn; cnz /= nn;
    }
    if (cnz > 0.0f) { cnx = -cnx; cny = -cny; cnz = -cnz; }

    float cux = cny * dz - cnz * dy_;
    float cuy = cnz * dx - cnx * dz;
    float cuz = cnx * dy_ - cny * dx;
    {
        float nn = sqrtf(cux * cux + cuy * cuy + cuz * cuz) + EPSF;
        cux /= nn; cuy /= nn; cuz /= nn;
    }

    int num_h = (int)floorf(cur_len / 0.05f);
    num_h = max(2, min(1000, num_h));

    if (threadIdx.x == 0) {
        float pdx = p0x - p2x, pdy = p0y - p2y, pdz = p0z - p2z;
        float pnx = pdy * dz - pdz * dy_;
        float pny = pdz * dx - pdx * dz;
        float pnz = pdx * dy_ - pdy * dx;
        float nn = sqrtf(pnx * pnx + pny * pny + pnz * pnz) + EPSF;
        float nl = 1.0f - (cnx * pnx + cny * pny + cnz * pnz) / nn;

        float onx = p0y * p1z - p0z * p1y;
        float ony = p0z * p1x - p0x * p1z;
        float onz = p0x * p1y - p0y * p1x;
        float on = sqrtf(onx * onx + ony * ony + onz * onz) + EPSF;
        float snp = fminf(fabsf((cux * onx + cuy * ony + cuz * onz) / on), 0.5f);
        float nz = 1.0f - snp / 0.5f;

        atomicAdd(&g_norm, (double)nl);
        atomicAdd(&g_normz, (double)nz);
        atomicAdd(&g_count, (unsigned long long)num_h);
    }

    float k00 = K1[0], k01 = K1[1], k02 = K1[2];
    float k10 = K1[3], k11 = K1[4], k12 = K1[5];
    float k20 = K1[6], k21 = K1[7], k22 = K1[8];
    float t00 = T[0],  t01 = T[1],  t02 = T[2],  t03 = T[3];
    float t10 = T[4],  t11 = T[5],  t12 = T[6],  t13 = T[7];
    float t20 = T[8],  t21 = T[9],  t22 = T[10], t23 = T[11];

    float step = cur_len / (float)(num_h - 1);
    int total = num_h * NUM_VV;
    double lsim = 0.0;

    for (int i = threadIdx.x; i < total; i += 128) {
        int px = i / NUM_VV;
        int dv = i - px * NUM_VV;
        float cx = (float)px * step;
        float cy = (float)dv * (0.5f / 9.0f);

        float ptx = dx * cx + cux * cy + p0x;
        float pty = dy_ * cx + cuy * cy + p0y;
        float ptz = dz * cx + cuz * cy + p0z;

        float z1 = k20 * ptx + k21 * pty + k22 * ptz;
        float u1 = clamp_uv((k00 * ptx + k01 * pty + k02 * ptz) / z1);
        float v1 = clamp_uv((k10 * ptx + k11 * pty + k12 * ptz) / z1);
        float s1a, s1b, s1c;
        sample3h(g_i1, u1, v1, s1a, s1b, s1c);

        float z2 = t20 * ptx + t21 * pty + t22 * ptz + t23;
        float u2 = clamp_uv((t00 * ptx + t01 * pty + t02 * ptz + t03) / z2);
        float v2 = clamp_uv((t10 * ptx + t11 * pty + t12 * ptz + t13) / z2);
        float s2a, s2b, s2c;
        sample3h(g_i2, u2, v2, s2a, s2b, s2c);

        float d0 = s1a - s2a, d1 = s1b - s2b, d2 = s1c - s2c;
        lsim += (double)(d0 * d0 + d1 * d1 + d2 * d2);
    }

    // block reduction
    for (int o = 16; o > 0; o >>= 1)
        lsim += __shfl_down_sync(0xffffffffu, lsim, o);
    __shared__ double ssum[4];
    int lane = threadIdx.x & 31;
    int w = threadIdx.x >> 5;
    if (lane == 0) ssum[w] = lsim;
    __syncthreads();
    if (threadIdx.x == 0) {
        double t = ssum[0] + ssum[1] + ssum[2] + ssum[3];
        atomicAdd(&g_sim, t);

        // last-block finalize
        __threadfence();
        unsigned int done = atomicAdd(&g_done, 1u);
        if (done == (unsigned int)gridDim.x - 1u) {
            double sim = g_sim, nrm = g_norm, nrz = g_normz;
            double cnt = (double)g_count * (double)NUM_VV * 3.0;
            out[0] = (float)(sim / cnt);
            out[1] = (float)(nrm / (double)N * 0.5);
            out[2] = (float)(nrz / (double)N);
            // reset for next invocation / replay
            g_sim = 0.0; g_norm = 0.0; g_normz = 0.0;
            g_count = 0ull; g_done = 0u;
        }
    }
}

// ---------------- launch -------------------------------------------------------
extern "C" void kernel_launch(void* const* d_in, const int* in_sizes, int n_in,
                              void* d_out, int out_size) {
    const float* ep   = (const float*)d_in[0];
    const float* K1   = (const float*)d_in[1];
    const float* K2   = (const float*)d_in[2];
    const float* E1   = (const float*)d_in[3];
    const float* E2   = (const float*)d_in[4];
    const float* rgb1 = (const float*)d_in[5];
    const float* rgb2 = (const float*)d_in[6];
    float* out = (float*)d_out;

    int N = in_sizes[0] / 12;

    repack_k<<<2048, 256>>>(rgb1, rgb2);
    edge_k<<<N, 128>>>(ep, K1, K2, E1, E2, out, N);
}